// round 1
// baseline (speedup 1.0000x reference)
#include <cuda_runtime.h>

// E8 quantizer, closed form.
//
// All 240 E8 roots have ||c||^2 = 2, so softmax(-(||x||^2 - 2 x.c + ||c||^2)/T)
// == softmax(beta * x.c) with beta = 2/T.  The root structure factorizes:
//
//  Type-1 (112 roots: +-1 at i, +-1 at j, i<j):
//     A_i = e^{beta x_i} + e^{-beta x_i},  B_i = e^{beta x_i} - e^{-beta x_i}
//     sum of weights            = sum_{i<j} A_i A_j
//     numerator (dim d)         = B_d * sum_{j != d} A_j
//
//  Type-2 (128 roots: (+-1/2)^8, even # of minus signs):
//     a_i = e^{beta x_i/2} + e^{-beta x_i/2},  b_i = e^{beta x_i/2} - e^{-beta x_i/2}
//     sum of weights            = (prod a_i + prod b_i) / 2
//     numerator (dim d)         = ( b_d * prod_{i!=d} a_i + a_d * prod_{i!=d} b_i ) / 4
//
//  A = a^2 - 2, B = a*b  (since hp*hn = 1), so only 16 EX2 per point.
//
// Exclusive sums/products are built from prefix+suffix passes (no large-term
// subtraction -> no catastrophic cancellation when one exp dominates).
// Roots come in +- pairs => max dot >= 0 => denominator >= 1, no max-shift needed.

#define BETA_HALF_LOG2E 4.8089834696568576f   // (2/0.3)/2 * log2(e)

__device__ __forceinline__ float ex2_approx(float x) {
    float y;
    asm("ex2.approx.ftz.f32 %0, %1;" : "=f"(y) : "f"(x));
    return y;
}

__device__ __forceinline__ float rcp_approx(float x) {
    float y;
    asm("rcp.approx.ftz.f32 %0, %1;" : "=f"(y) : "f"(x));
    return y;
}

__global__ void __launch_bounds__(256) e8_quantize_kernel(
    const float* __restrict__ x, float* __restrict__ out, int n)
{
    int p = blockIdx.x * blockDim.x + threadIdx.x;
    if (p >= n) return;

    const float4* x4 = reinterpret_cast<const float4*>(x);
    float4 v0 = x4[2 * p + 0];
    float4 v1 = x4[2 * p + 1];
    float xi[8] = {v0.x, v0.y, v0.z, v0.w, v1.x, v1.y, v1.z, v1.w};

    float a[8], b[8], A[8], B[8];
#pragma unroll
    for (int i = 0; i < 8; i++) {
        float t  = xi[i] * BETA_HALF_LOG2E;   // beta*x/2 in log2 domain
        float hp = ex2_approx(t);             // e^{ beta x_i / 2}
        float hn = ex2_approx(-t);            // e^{-beta x_i / 2}
        a[i] = hp + hn;
        b[i] = hp - hn;
        A[i] = fmaf(a[i], a[i], -2.0f);       // e^{beta x} + e^{-beta x}
        B[i] = a[i] * b[i];                   // e^{beta x} - e^{-beta x}
    }

    // prefix/suffix sums of A (all positive; no cancellation)
    float preS[9], sufS[9];
    preS[0] = 0.0f; sufS[8] = 0.0f;
#pragma unroll
    for (int i = 0; i < 8; i++)  preS[i + 1] = preS[i] + A[i];
#pragma unroll
    for (int i = 7; i >= 0; i--) sufS[i] = sufS[i + 1] + A[i];

    // D1 = sum_{i<j} A_i A_j
    float D1 = 0.0f;
#pragma unroll
    for (int i = 0; i < 8; i++)  D1 = fmaf(A[i], sufS[i + 1], D1);

    // prefix/suffix products of a and b
    float pa[9], sa[9], pb[9], sb[9];
    pa[0] = 1.0f; pb[0] = 1.0f; sa[8] = 1.0f; sb[8] = 1.0f;
#pragma unroll
    for (int i = 0; i < 8; i++)  { pa[i + 1] = pa[i] * a[i]; pb[i + 1] = pb[i] * b[i]; }
#pragma unroll
    for (int i = 7; i >= 0; i--) { sa[i] = sa[i + 1] * a[i]; sb[i] = sb[i + 1] * b[i]; }

    float D  = D1 + 0.5f * (pa[8] + pb[8]);
    float rD = rcp_approx(D);

    float o[8];
#pragma unroll
    for (int d = 0; d < 8; d++) {
        float SAe = preS[d] + sufS[d + 1];       // sum_{j != d} A_j
        float PaE = pa[d] * sa[d + 1];           // prod_{i != d} a_i
        float PbE = pb[d] * sb[d + 1];           // prod_{i != d} b_i
        float num = fmaf(B[d], SAe,
                         0.25f * fmaf(b[d], PaE, a[d] * PbE));
        o[d] = num * rD;
    }

    float4* o4 = reinterpret_cast<float4*>(out);
    o4[2 * p + 0] = make_float4(o[0], o[1], o[2], o[3]);
    o4[2 * p + 1] = make_float4(o[4], o[5], o[6], o[7]);
}

extern "C" void kernel_launch(void* const* d_in, const int* in_sizes, int n_in,
                              void* d_out, int out_size) {
    const float* x = (const float*)d_in[0];   // [N, 8] fp32
    float* out = (float*)d_out;               // [N, 8] fp32
    int n = in_sizes[0] / 8;
    int block = 256;
    int grid = (n + block - 1) / block;
    e8_quantize_kernel<<<grid, block>>>(x, out, n);
}